// round 8
// baseline (speedup 1.0000x reference)
#include <cuda_runtime.h>

#define Bsz 512
#define Tt  128
#define Ff  256
#define Hh  384
#define Ll  3
#define Kw  10
#define LAB 25
#define GATES 1542   // 4*H + 2*L
#define NHT 32       // h-tiles in fused kernel
#define HT  12       // hcols per tile (32*12 = 384)

// ---------------- device scratch ----------------
__device__ float g_xw[(size_t)Bsz * Tt * GATES];   // X@kw + kb + rb (+t-rows), per (b,t)
__device__ float g_h2[2][Bsz * Hh];                // parity-buffered hidden state
__device__ float g_c[Bsz * Hh];
__device__ float g_hhist[(size_t)Tt * Bsz * Hh];
__device__ float g_dist[Tt * Bsz];
__device__ float g_p6[2][NHT][Bsz][6];             // parity-buffered partial h@rw[:,0:6]

typedef unsigned long long ull;
__device__ __forceinline__ ull splat2(float x) {
    ull r; asm("mov.b64 %0, {%1, %1};" : "=l"(r) : "f"(x)); return r;
}
__device__ __forceinline__ void fma2(ull& d, ull a, ull b) {
    asm("fma.rn.f32x2 %0, %1, %2, %3;" : "=l"(d) : "l"(a), "l"(b), "l"(d));
}
__device__ __forceinline__ float2 unpk(ull v) {
    float2 r; asm("mov.b64 {%0, %1}, %2;" : "=f"(r.x), "=f"(r.y) : "l"(v)); return r;
}
__device__ __forceinline__ float sigf(float x) { return 1.0f / (1.0f + __expf(-x)); }
__device__ __forceinline__ float tanhfast(float x) { return 1.0f - 2.0f / (1.0f + __expf(2.0f * x)); }

// ---------------- init: zero h, c, p6 (both parities; replayed each graph run) ----
__global__ void init_state() {
    float* p6f = (float*)g_p6;  // 2*32*512*6 = 196608 floats
    for (int i = blockIdx.x * blockDim.x + threadIdx.x; i < Bsz * Hh;
         i += gridDim.x * blockDim.x) {
        g_h2[0][i] = 0.0f; g_h2[1][i] = 0.0f; g_c[i] = 0.0f; p6f[i] = 0.0f;
    }
}

// ============ gemm_xw: g_xw = [X, t>0] @ kernel_w + kernel_b + rec_b (+t-rows) =====
// M=65536, K=256, N=1542. 128x128 tile, BK=16, f32x2 row-pair accumulators.
__global__ __launch_bounds__(256, 2) void gemm_xw(const float* __restrict__ X,
                                                  const float* __restrict__ kw,
                                                  const float* __restrict__ kbias,
                                                  const float* __restrict__ rw,
                                                  const float* __restrict__ rbias) {
    __shared__ __align__(16) float As[2][16][128];
    __shared__ __align__(16) float Bs[2][16][128];
    const int bn = blockIdx.x * 128, bm = blockIdx.y * 128;
    const int tid = threadIdx.x;
    const int tm = (tid >> 4) << 3, tn = (tid & 15) << 3;
    const int a_r = tid >> 2, a_k4 = (tid & 3) * 4;
    const int b_k = tid >> 6, b_n = (tid & 63) * 2;

    float4 pa[2]; float2 pb[4];
    ull acc2[4][8] = {};   // row-pairs (tm+2ip, tm+2ip+1) x cols (tn+j)

    auto ldA = [&](int k0) {
#pragma unroll
        for (int r = 0; r < 2; r++)
            pa[r] = *(const float4*)(X + (size_t)(bm + a_r + 64 * r) * Ff + k0 + a_k4);
    };
    auto ldB = [&](int k0) {
#pragma unroll
        for (int r = 0; r < 4; r++) {
            int n = bn + b_n;
            float2 v = make_float2(0.0f, 0.0f);
            if (n < GATES) v = *(const float2*)(kw + (size_t)(k0 + b_k + 4 * r) * GATES + n);
            pb[r] = v;
        }
    };
    auto stA = [&](int buf) {
#pragma unroll
        for (int r = 0; r < 2; r++) {
            As[buf][a_k4 + 0][a_r + 64 * r] = pa[r].x;
            As[buf][a_k4 + 1][a_r + 64 * r] = pa[r].y;
            As[buf][a_k4 + 2][a_r + 64 * r] = pa[r].z;
            As[buf][a_k4 + 3][a_r + 64 * r] = pa[r].w;
        }
    };
    auto stB = [&](int buf) {
#pragma unroll
        for (int r = 0; r < 4; r++) {
            Bs[buf][b_k + 4 * r][b_n] = pb[r].x;
            Bs[buf][b_k + 4 * r][b_n + 1] = pb[r].y;
        }
    };

    const int NB = Ff / 16;
    ldA(0); ldB(0); stA(0); stB(0);
    __syncthreads();
    for (int kblk = 0; kblk < NB; kblk++) {
        int nxt = kblk + 1;
        if (nxt < NB) { ldA(nxt * 16); ldB(nxt * 16); }
        int p = kblk & 1;
#pragma unroll
        for (int kk = 0; kk < 16; kk++) {
            ulonglong2 a01 = *(const ulonglong2*)&As[p][kk][tm];
            ulonglong2 a23 = *(const ulonglong2*)&As[p][kk][tm + 4];
            float4 b0 = *(const float4*)&Bs[p][kk][tn];
            float4 b1 = *(const float4*)&Bs[p][kk][tn + 4];
            ull ar[4] = {a01.x, a01.y, a23.x, a23.y};
            ull bs[8] = {splat2(b0.x), splat2(b0.y), splat2(b0.z), splat2(b0.w),
                         splat2(b1.x), splat2(b1.y), splat2(b1.z), splat2(b1.w)};
#pragma unroll
            for (int ip = 0; ip < 4; ip++)
#pragma unroll
                for (int j = 0; j < 8; j++) fma2(acc2[ip][j], ar[ip], bs[j]);
        }
        if (nxt < NB) { int q = nxt & 1; stA(q); stB(q); }
        __syncthreads();
    }
#pragma unroll
    for (int j = 0; j < 8; j++) {
        int n = bn + tn + j;
        if (n >= GATES) continue;
        float base = kbias[n] + rbias[n];
        float tadd = kw[(size_t)Ff * GATES + n] + rw[(size_t)Hh * GATES + n];
#pragma unroll
        for (int ip = 0; ip < 4; ip++) {
            int m0 = bm + tm + ip * 2;
            float2 v = unpk(acc2[ip][j]);
            int t0 = m0 & (Tt - 1), t1 = (m0 + 1) & (Tt - 1);
            g_xw[(size_t)m0 * GATES + n]       = v.x + base + (t0 > 0 ? tadd : 0.0f);
            g_xw[(size_t)(m0 + 1) * GATES + n] = v.y + base + (t1 > 0 ? tadd : 0.0f);
        }
    }
}

// ============ fused_step: xo-gates GEMM + softmax6 + state update, one launch/step ==
// Grid (32 h-tiles, 4 batch-tiles), 192 threads. Tile: 128 rows x 12 hcols x 4 gates.
// Thread: trow=tid%16 (8 rows), tcol=tid/16 (1 hcol, all 4 gates). BK=24, 16 k-blocks.
__global__ __launch_bounds__(192) void fused_step(const float* __restrict__ rw, int t) {
    __shared__ __align__(16) float As[2][24][128];
    __shared__ __align__(16) float Bs[2][24][48];
    __shared__ float fis[128][8];      // F0..2, I0..2 per local row
    __shared__ float p6sum[128][6];    // this CTA's partial h_new @ rw[:,0:6]
    __shared__ float rw6s[HT][6];

    const int tid = threadIdx.x;
    const int ht = blockIdx.x;
    const int bm = blockIdx.y * 128;
    const int trow = tid & 15, tcol = tid >> 4;
    const int rd = t & 1, wr = 1 - rd;
    const float* hsrc = g_h2[rd];

    for (int i = tid; i < 128 * 6; i += 192) p6sum[i / 6][i % 6] = 0.0f;
    if (tid < HT * 6) rw6s[tid / 6][tid % 6] = rw[(size_t)(ht * HT + tid / 6) * GATES + (tid % 6)];

    float4 pa[4]; float2 pb[3];
    ull acc2[4][4] = {};   // row-pairs (trow*8+2ip, +1) x gates

    auto ldA = [&](int kb) {
#pragma unroll
        for (int r = 0; r < 4; r++) {
            int idx = tid + 192 * r;           // 768 float4s = 128 rows x 6
            int row = idx / 6, kq = idx % 6;
            pa[r] = *(const float4*)(hsrc + (size_t)(bm + row) * Hh + kb * 24 + kq * 4);
        }
    };
    auto stA = [&](int buf) {
#pragma unroll
        for (int r = 0; r < 4; r++) {
            int idx = tid + 192 * r;
            int row = idx / 6, kq4 = (idx % 6) * 4;
            As[buf][kq4 + 0][row] = pa[r].x;
            As[buf][kq4 + 1][row] = pa[r].y;
            As[buf][kq4 + 2][row] = pa[r].z;
            As[buf][kq4 + 3][row] = pa[r].w;
        }
    };
    auto ldB = [&](int kb) {
#pragma unroll
        for (int r = 0; r < 3; r++) {
            int idx = tid + 192 * r;           // 576 float2s = 24k x 24
            int k = idx / 24, p = idx % 24;
            int g = p & 3, hp = p >> 2;
            pb[r] = *(const float2*)(rw + (size_t)(kb * 24 + k) * GATES
                                     + 6 + g * 384 + ht * HT + hp * 2);
        }
    };
    auto stB = [&](int buf) {
#pragma unroll
        for (int r = 0; r < 3; r++) {
            int idx = tid + 192 * r;
            int k = idx / 24, p = idx % 24;
            int g = p & 3, hp = p >> 2;
            Bs[buf][k][hp * 8 + g]     = pb[r].x;
            Bs[buf][k][hp * 8 + 4 + g] = pb[r].y;
        }
    };

    ldA(0); ldB(0); stA(0); stB(0);
    __syncthreads();
    for (int kb = 0; kb < 16; kb++) {
        if (kb < 15) { ldA(kb + 1); ldB(kb + 1); }
        int p = kb & 1;
#pragma unroll
        for (int kk = 0; kk < 24; kk++) {
            ulonglong2 a01 = *(const ulonglong2*)&As[p][kk][trow * 8];
            ulonglong2 a23 = *(const ulonglong2*)&As[p][kk][trow * 8 + 4];
            float4 bv = *(const float4*)&Bs[p][kk][tcol * 4];
            ull bs0 = splat2(bv.x), bs1 = splat2(bv.y), bs2 = splat2(bv.z), bs3 = splat2(bv.w);
            fma2(acc2[0][0], a01.x, bs0); fma2(acc2[0][1], a01.x, bs1);
            fma2(acc2[0][2], a01.x, bs2); fma2(acc2[0][3], a01.x, bs3);
            fma2(acc2[1][0], a01.y, bs0); fma2(acc2[1][1], a01.y, bs1);
            fma2(acc2[1][2], a01.y, bs2); fma2(acc2[1][3], a01.y, bs3);
            fma2(acc2[2][0], a23.x, bs0); fma2(acc2[2][1], a23.x, bs1);
            fma2(acc2[2][2], a23.x, bs2); fma2(acc2[2][3], a23.x, bs3);
            fma2(acc2[3][0], a23.y, bs0); fma2(acc2[3][1], a23.y, bs1);
            fma2(acc2[3][2], a23.y, bs2); fma2(acc2[3][3], a23.y, bs3);
        }
        if (kb < 15) { int q = (kb + 1) & 1; stA(q); stB(q); }
        __syncthreads();
    }

    // unpack + add xw (already contains kb + rb + t-row terms)
    const int h_g = ht * HT + tcol;
    const int l = h_g >> 7;
    float fa[8][4];
#pragma unroll
    for (int ip = 0; ip < 4; ip++)
#pragma unroll
        for (int j = 0; j < 4; j++) {
            float2 v = unpk(acc2[ip][j]);
            fa[2 * ip][j] = v.x; fa[2 * ip + 1][j] = v.y;
        }
#pragma unroll
    for (int i = 0; i < 8; i++) {
        int b = bm + trow * 8 + i;
        const float* xr = g_xw + ((size_t)b * Tt + t) * GATES;
#pragma unroll
        for (int j = 0; j < 4; j++) fa[i][j] += xr[6 + j * 384 + h_g];
    }

    // per-row softmax6 (one thread per row): a = xw[0:6] + sum of 32 h-tile partials
    if (tid < 128) {
        int b = bm + tid;
        const float* xr = g_xw + ((size_t)b * Tt + t) * GATES;
        float a0 = xr[0], a1 = xr[1], a2 = xr[2], a3 = xr[3], a4 = xr[4], a5 = xr[5];
#pragma unroll 8
        for (int p2 = 0; p2 < NHT; p2++) {
            const float* pp = &g_p6[rd][p2][b][0];
            a0 += pp[0]; a1 += pp[1]; a2 += pp[2];
            a3 += pp[3]; a4 += pp[4]; a5 += pp[5];
        }
        float m1 = fmaxf(a0, fmaxf(a1, a2));
        float e0 = __expf(a0 - m1), e1 = __expf(a1 - m1), e2 = __expf(a2 - m1);
        float inv = 1.0f / (e0 + e1 + e2);
        float f0 = e0 * inv, f1 = (e0 + e1) * inv, f2 = (e0 + e1 + e2) * inv;
        float m2 = fmaxf(a3, fmaxf(a4, a5));
        float q0 = __expf(a3 - m2), q1 = __expf(a4 - m2), q2 = __expf(a5 - m2);
        float inv2 = 1.0f / (q0 + q1 + q2);
        fis[tid][0] = f0; fis[tid][1] = f1; fis[tid][2] = f2;
        fis[tid][3] = (q0 + q1 + q2) * inv2;
        fis[tid][4] = (q1 + q2) * inv2;
        fis[tid][5] = q2 * inv2;
        if (ht == 0) g_dist[t * Bsz + b] = 1.0f - (f0 + f1 + f2) * (1.0f / 3.0f);
    }
    __syncthreads();

    // gate nonlinearities + c/h update + next-step partial6
#pragma unroll
    for (int i = 0; i < 8; i++) {
        int row = trow * 8 + i;
        int b = bm + row;
        float F = fis[row][l], I = fis[row][3 + l];
        float fg = sigf(fa[i][0]);
        float ig = sigf(fa[i][1]);
        float og = sigf(fa[i][2]);
        float ci = tanhfast(fa[i][3]);
        float cold = g_c[(size_t)b * Hh + h_g];
        float ov = F * I;
        float cn = ov * (fg * cold + ig * ci) + (F - ov) * cold + (I - ov) * ci;
        g_c[(size_t)b * Hh + h_g] = cn;
        float hn = og * tanhfast(cn);
        g_h2[wr][(size_t)b * Hh + h_g] = hn;
        g_hhist[((size_t)t * Bsz + b) * Hh + h_g] = hn;
#pragma unroll
        for (int c = 0; c < 6; c++) atomicAdd(&p6sum[row][c], hn * rw6s[tcol][c]);
    }
    __syncthreads();
    for (int i = tid; i < 128 * 6; i += 192)
        g_p6[wr][ht][bm + i / 6][i % 6] = p6sum[i / 6][i % 6];
}

// ---------------- finalize: per-batch theme/conv/out at t = v_len-1 ----------------
#define GROUP 4
#define FIN_SMEM_FLOATS (GROUP * 3840 + GROUP * Hh + GROUP * Hh + GROUP * 64 + GROUP * Kw + GROUP * Kw + GROUP)
__global__ __launch_bounds__(384) void finalize(
    const int* __restrict__ vlen,
    const float* __restrict__ sw, const float* __restrict__ sb,
    const float* __restrict__ rsw, const float* __restrict__ rsb,
    const float* __restrict__ cw, const float* __restrict__ cb,
    const float* __restrict__ ow, const float* __restrict__ ob,
    float* __restrict__ out) {
    extern __shared__ float sm[];
    float* lh   = sm;
    float* th   = lh + GROUP * 3840;
    float* rn   = th + GROUP * Hh;
    float* s1   = rn + GROUP * Hh;
    float* ldw  = s1 + GROUP * 64;
    float* dtmp = ldw + GROUP * Kw;
    int*   tbs  = (int*)(dtmp + GROUP * Kw);

    const int tid = threadIdx.x;
    const int b0 = blockIdx.x * GROUP;

    if (tid < GROUP) tbs[tid] = vlen[b0 + tid] - 1;
    __syncthreads();
    if (tid < GROUP * Kw) {
        int g = tid / Kw, j = tid % Kw;
        int ts = tbs[g] - (Kw - 1) + j;
        dtmp[g * Kw + j] = (ts >= 0) ? g_dist[ts * Bsz + b0 + g] : 0.0f;
    }
    __syncthreads();
    if (tid < GROUP) {
        float c = 0.0f, cums[Kw];
#pragma unroll
        for (int j = 0; j < Kw; j++) { c += dtmp[tid * Kw + j]; cums[j] = c; }
        float m = cums[Kw - 1];
        float s = 0.0f, e[Kw];
#pragma unroll
        for (int j = 0; j < Kw; j++) { e[j] = __expf(cums[j] - m); s += e[j]; }
        float inv = 1.0f / s;
#pragma unroll
        for (int j = 0; j < Kw; j++) ldw[tid * Kw + j] = e[j] * inv;
    }
    __syncthreads();

    for (int g = 0; g < GROUP; g++) {
        int tb = tbs[g], b = b0 + g;
        float tr = 0.0f;
#pragma unroll
        for (int j = 0; j < Kw; j++) {
            int ts = tb - (Kw - 1) + j;
            float hv = (ts >= 0) ? g_hhist[((size_t)ts * Bsz + b) * Hh + tid] : 0.0f;
            float v = hv * ldw[g * Kw + j];
            lh[g * 3840 + j * Hh + tid] = v;
            tr += v;
        }
        th[g * Hh + tid] = tr * 0.1f;
    }
    __syncthreads();

    if (tid < GROUP * 64) {
        int g = tid >> 6, j = tid & 63;
        float a = sb[j];
        for (int h = 0; h < Hh; h++) a += th[g * Hh + h] * sw[h * 64 + j];
        s1[g * 64 + j] = fmaxf(a, 0.0f);
    }
    __syncthreads();

    float accv[GROUP];
    float cbv = cb[tid];
#pragma unroll
    for (int g = 0; g < GROUP; g++) accv[g] = cbv;
    const float2* cwp = (const float2*)(cw + (size_t)tid * (Hh * Kw));
    for (int h = 0; h < Hh; h++) {
#pragma unroll
        for (int jp = 0; jp < Kw / 2; jp++) {
            float2 w = cwp[h * (Kw / 2) + jp];
            int j0 = jp * 2;
#pragma unroll
            for (int g = 0; g < GROUP; g++) {
                accv[g] += lh[g * 3840 + j0 * Hh + h] * w.x
                         + lh[g * 3840 + (j0 + 1) * Hh + h] * w.y;
            }
        }
    }

    for (int g = 0; g < GROUP; g++) {
        float a = rsb[tid];
#pragma unroll
        for (int j = 0; j < 64; j++) a += s1[g * 64 + j] * rsw[j * Hh + tid];
        float t2 = sigf(a);
        int tb = tbs[g], b = b0 + g;
        float hf = g_hhist[((size_t)tb * Bsz + b) * Hh + tid];
        rn[g * Hh + tid] = hf + t2 * accv[g];
    }
    __syncthreads();

    if (tid < GROUP * LAB) {
        int g = tid / LAB, lab = tid % LAB;
        float a = ob[lab];
        for (int h = 0; h < Hh; h++) a += rn[g * Hh + h] * ow[h * LAB + lab];
        out[(b0 + g) * LAB + lab] = a;
    }
}

// ---------------- launch ----------------
extern "C" void kernel_launch(void* const* d_in, const int* in_sizes, int n_in,
                              void* d_out, int out_size) {
    const float* X   = (const float*)d_in[0];
    const int*   vlen= (const int*)  d_in[1];
    const float* kw  = (const float*)d_in[2];
    const float* kb  = (const float*)d_in[3];
    const float* rw  = (const float*)d_in[4];
    const float* rb  = (const float*)d_in[5];
    const float* sw  = (const float*)d_in[6];
    const float* sb  = (const float*)d_in[7];
    const float* rsw = (const float*)d_in[8];
    const float* rsb = (const float*)d_in[9];
    const float* cw  = (const float*)d_in[10];
    const float* cb  = (const float*)d_in[11];
    const float* ow  = (const float*)d_in[12];
    const float* ob  = (const float*)d_in[13];
    float* out = (float*)d_out;

    cudaFuncSetAttribute(finalize, cudaFuncAttributeMaxDynamicSharedMemorySize,
                         FIN_SMEM_FLOATS * (int)sizeof(float));

    init_state<<<96, 512>>>();
    gemm_xw<<<dim3((GATES + 127) / 128, (Bsz * Tt) / 128), 256>>>(X, kw, kb, rw, rb);
    for (int t = 0; t < Tt; t++) {
        fused_step<<<dim3(NHT, Bsz / 128), 192>>>(rw, t);
    }
    finalize<<<Bsz / GROUP, Hh, FIN_SMEM_FLOATS * (int)sizeof(float)>>>(
        vlen, sw, sb, rsw, rsb, cw, cb, ow, ob, out);
}

// round 10
// speedup vs baseline: 1.6872x; 1.6872x over previous
#include <cuda_runtime.h>

#define Bsz 512
#define Tt  128
#define Ff  256
#define Hh  384
#define Ll  3
#define Kw  10
#define LAB 25
#define GATES 1542   // 4*H + 2*L
#define NHT 32       // n-tiles (each 12 hcols x 4 gates = 48 gate cols)
#define HT  12
#define NTW 48
#define BKF 48       // A k-block
#define NKB 8        // 384 / 48

// ---------------- device scratch ----------------
__device__ __align__(16) float g_xw[(size_t)Bsz * Tt * GATES];    // [b*T+t][n]
__device__ __align__(16) float g_xwT[(size_t)Tt * GATES * Bsz];   // [t][n][b]
__device__ __align__(16) float g_hT[2][Hh][Bsz];                  // parity h, transposed
__device__ __align__(16) float g_cT[Hh][Bsz];
__device__ __align__(16) float g_hhistT[(size_t)Tt * Hh * Bsz];   // [t][h][b]
__device__ __align__(16) float g_dist[Tt * Bsz];
__device__ __align__(16) float g_p6s[3][Bsz][8];                  // 3-phase h@rw[:,0:6] sums
__device__ __align__(16) float g_Brep[NHT][Hh][NTW];              // repacked rec_w gate cols

typedef unsigned long long ull;
__device__ __forceinline__ ull splat2(float x) {
    ull r; asm("mov.b64 %0, {%1, %1};" : "=l"(r) : "f"(x)); return r;
}
__device__ __forceinline__ void fma2(ull& d, ull a, ull b) {
    asm("fma.rn.f32x2 %0, %1, %2, %3;" : "=l"(d) : "l"(a), "l"(b), "l"(d));
}
__device__ __forceinline__ float2 unpk(ull v) {
    float2 r; asm("mov.b64 {%0, %1}, %2;" : "=f"(r.x), "=f"(r.y) : "l"(v)); return r;
}
__device__ __forceinline__ float sigf(float x) { return 1.0f / (1.0f + __expf(-x)); }
__device__ __forceinline__ float tanhfast(float x) { return 1.0f - 2.0f / (1.0f + __expf(2.0f * x)); }

// ---------------- init ----------------
__global__ void init_state() {
    int stride = gridDim.x * blockDim.x;
    int tid0 = blockIdx.x * blockDim.x + threadIdx.x;
    float* h = &g_hT[0][0][0];
    for (int i = tid0; i < 2 * Hh * Bsz; i += stride) h[i] = 0.0f;
    float* c = &g_cT[0][0];
    for (int i = tid0; i < Hh * Bsz; i += stride) c[i] = 0.0f;
    float* p = &g_p6s[0][0][0];
    for (int i = tid0; i < 3 * Bsz * 8; i += stride) p[i] = 0.0f;
}

// ---------------- prep_B: repack rec_w gate cols into [ht][k][hc*4+j] ----------------
__global__ void prep_B(const float* __restrict__ rw) {
    int idx = blockIdx.x * blockDim.x + threadIdx.x;
    if (idx >= NHT * Hh * NTW) return;
    int ht = idx / (Hh * NTW);
    int rem = idx % (Hh * NTW);
    int k = rem / NTW, c = rem % NTW;
    int hc = c >> 2, j = c & 3;
    (&g_Brep[0][0][0])[idx] = rw[(size_t)k * GATES + 6 + j * Hh + ht * HT + hc];
}

// ============ gemm_xw: g_xw = [X, t>0] @ kernel_w + kernel_b + rec_b (+t-rows) =====
__global__ __launch_bounds__(256, 2) void gemm_xw(const float* __restrict__ X,
                                                  const float* __restrict__ kw,
                                                  const float* __restrict__ kbias,
                                                  const float* __restrict__ rw,
                                                  const float* __restrict__ rbias) {
    __shared__ __align__(16) float As[2][16][128];
    __shared__ __align__(16) float Bs[2][16][128];
    const int bn = blockIdx.x * 128, bm = blockIdx.y * 128;
    const int tid = threadIdx.x;
    const int tm = (tid >> 4) << 3, tn = (tid & 15) << 3;
    const int a_r = tid >> 2, a_k4 = (tid & 3) * 4;
    const int b_k = tid >> 6, b_n = (tid & 63) * 2;

    float4 pa[2]; float2 pb[4];
    ull acc2[4][8] = {};

    auto ldA = [&](int k0) {
#pragma unroll
        for (int r = 0; r < 2; r++)
            pa[r] = *(const float4*)(X + (size_t)(bm + a_r + 64 * r) * Ff + k0 + a_k4);
    };
    auto ldB = [&](int k0) {
#pragma unroll
        for (int r = 0; r < 4; r++) {
            int n = bn + b_n;
            float2 v = make_float2(0.0f, 0.0f);
            if (n < GATES) v = *(const float2*)(kw + (size_t)(k0 + b_k + 4 * r) * GATES + n);
            pb[r] = v;
        }
    };
    auto stA = [&](int buf) {
#pragma unroll
        for (int r = 0; r < 2; r++) {
            As[buf][a_k4 + 0][a_r + 64 * r] = pa[r].x;
            As[buf][a_k4 + 1][a_r + 64 * r] = pa[r].y;
            As[buf][a_k4 + 2][a_r + 64 * r] = pa[r].z;
            As[buf][a_k4 + 3][a_r + 64 * r] = pa[r].w;
        }
    };
    auto stB = [&](int buf) {
#pragma unroll
        for (int r = 0; r < 4; r++) {
            Bs[buf][b_k + 4 * r][b_n] = pb[r].x;
            Bs[buf][b_k + 4 * r][b_n + 1] = pb[r].y;
        }
    };

    const int NB = Ff / 16;
    ldA(0); ldB(0); stA(0); stB(0);
    __syncthreads();
    for (int kblk = 0; kblk < NB; kblk++) {
        int nxt = kblk + 1;
        if (nxt < NB) { ldA(nxt * 16); ldB(nxt * 16); }
        int p = kblk & 1;
#pragma unroll
        for (int kk = 0; kk < 16; kk++) {
            ulonglong2 a01 = *(const ulonglong2*)&As[p][kk][tm];
            ulonglong2 a23 = *(const ulonglong2*)&As[p][kk][tm + 4];
            float4 b0 = *(const float4*)&Bs[p][kk][tn];
            float4 b1 = *(const float4*)&Bs[p][kk][tn + 4];
            ull ar[4] = {a01.x, a01.y, a23.x, a23.y};
            ull bs[8] = {splat2(b0.x), splat2(b0.y), splat2(b0.z), splat2(b0.w),
                         splat2(b1.x), splat2(b1.y), splat2(b1.z), splat2(b1.w)};
#pragma unroll
            for (int ip = 0; ip < 4; ip++)
#pragma unroll
                for (int j = 0; j < 8; j++) fma2(acc2[ip][j], ar[ip], bs[j]);
        }
        if (nxt < NB) { int q = nxt & 1; stA(q); stB(q); }
        __syncthreads();
    }
#pragma unroll
    for (int j = 0; j < 8; j++) {
        int n = bn + tn + j;
        if (n >= GATES) continue;
        float base = kbias[n] + rbias[n];
        float tadd = kw[(size_t)Ff * GATES + n] + rw[(size_t)Hh * GATES + n];
#pragma unroll
        for (int ip = 0; ip < 4; ip++) {
            int m0 = bm + tm + ip * 2;
            float2 v = unpk(acc2[ip][j]);
            int t0 = m0 & (Tt - 1), t1 = (m0 + 1) & (Tt - 1);
            g_xw[(size_t)m0 * GATES + n]       = v.x + base + (t0 > 0 ? tadd : 0.0f);
            g_xw[(size_t)(m0 + 1) * GATES + n] = v.y + base + (t1 > 0 ? tadd : 0.0f);
        }
    }
}

// ---------------- transpose_xw: g_xw[b*T+t][n] -> g_xwT[t][n][b] ----------------
__global__ __launch_bounds__(256) void transpose_xw() {
    __shared__ float tile[32][33];
    const int n0 = blockIdx.x * 32, b0 = blockIdx.y * 32, t = blockIdx.z;
    const int tx = threadIdx.x & 31, ty = threadIdx.x >> 5;
#pragma unroll
    for (int i = 0; i < 4; i++) {
        int b = b0 + ty + i * 8;
        int n = n0 + tx;
        float v = 0.0f;
        if (n < GATES) v = g_xw[((size_t)b * Tt + t) * GATES + n];
        tile[ty + i * 8][tx] = v;
    }
    __syncthreads();
#pragma unroll
    for (int i = 0; i < 4; i++) {
        int n = n0 + ty + i * 8;
        if (n < GATES)
            g_xwT[((size_t)t * GATES + n) * Bsz + b0 + tx] = tile[tx][ty + i * 8];
    }
}

// ============ fused_step: gates GEMM + softmax6 + state update, one launch/step ====
// Grid (32 n-tiles, 4 b-tiles), 384 threads (12 warps, balanced 3/SMSP).
__global__ __launch_bounds__(384, 1) void fused_step(const float* __restrict__ rw, int t) {
    extern __shared__ float sm[];
    float* Bs  = sm;                    // [384][52]      19968
    float* As  = Bs + 384 * 52;         // [2][48][128]   12288
    float* xs  = As + 2 * 48 * 128;     // [48][128]       6144
    float* p6p = xs + 48 * 128;         // [12][130][6]    9360
    float* fis = p6p + 12 * 130 * 6;    // [128][6]         768
    float* rw6 = fis + 128 * 6;         // [12][6]           72

    const int tid = threadIdx.x;
    const int ht = blockIdx.x, bm = blockIdx.y * 128;
    const int trow = tid & 15, tcol = tid >> 4;
    const int rd = t & 1, wr = rd ^ 1;
    const float* hsrc = &g_hT[rd][0][0];

    // ---- phase A: resident loads + prev-step softmax ----
    {
        const float4* src = (const float4*)&g_Brep[ht][0][0];   // 4608 float4
#pragma unroll
        for (int r = 0; r < 12; r++) {
            int idx = tid + 384 * r;
            float4 v = src[idx];
            int k = idx / 12, c4 = idx % 12;
            *(float4*)&Bs[k * 52 + c4 * 4] = v;
        }
    }
#pragma unroll
    for (int r = 0; r < 4; r++) {       // xw tile [c][b], 1536 float4
        int idx = tid + 384 * r;
        int c = idx >> 5, bq = idx & 31;
        int hc = c >> 2, j = c & 3;
        const float4* src = (const float4*)(g_xwT
            + ((size_t)t * GATES + 6 + j * Hh + ht * HT + hc) * Bsz + bm);
        *(float4*)&xs[c * 128 + bq * 4] = src[bq];
    }
    if (tid < HT * 6)
        rw6[tid] = rw[(size_t)(ht * HT + tid / 6) * GATES + (tid % 6)];

    float4 pa[4];
    auto ldA = [&](int blk) {
#pragma unroll
        for (int r = 0; r < 4; r++) {
            int idx = tid + 384 * r;
            int kr = idx >> 5, bq = idx & 31;
            pa[r] = *(const float4*)(hsrc + (size_t)(blk * BKF + kr) * Bsz + bm + bq * 4);
        }
    };
    auto stA = [&](int buf) {
#pragma unroll
        for (int r = 0; r < 4; r++) {
            int idx = tid + 384 * r;
            int kr = idx >> 5, bq = idx & 31;
            *(float4*)&As[(buf * 48 + kr) * 128 + bq * 4] = pa[r];
        }
    };
    ldA(0); stA(0);

    if (tid < 128) {   // softmax from prev-step p6 (3-phase buffer) + xw cols 0..5
        int b = bm + tid;
        const float* pp = &g_p6s[t % 3][b][0];
        float a0 = g_xwT[((size_t)t * GATES + 0) * Bsz + b] + pp[0];
        float a1 = g_xwT[((size_t)t * GATES + 1) * Bsz + b] + pp[1];
        float a2 = g_xwT[((size_t)t * GATES + 2) * Bsz + b] + pp[2];
        float a3 = g_xwT[((size_t)t * GATES + 3) * Bsz + b] + pp[3];
        float a4 = g_xwT[((size_t)t * GATES + 4) * Bsz + b] + pp[4];
        float a5 = g_xwT[((size_t)t * GATES + 5) * Bsz + b] + pp[5];
        float m1 = fmaxf(a0, fmaxf(a1, a2));
        float e0 = __expf(a0 - m1), e1 = __expf(a1 - m1), e2 = __expf(a2 - m1);
        float inv = 1.0f / (e0 + e1 + e2);
        float f0 = e0 * inv, f1 = (e0 + e1) * inv, f2 = (e0 + e1 + e2) * inv;
        float m2 = fmaxf(a3, fmaxf(a4, a5));
        float q0 = __expf(a3 - m2), q1 = __expf(a4 - m2), q2 = __expf(a5 - m2);
        float inv2 = 1.0f / (q0 + q1 + q2);
        fis[tid * 6 + 0] = f0; fis[tid * 6 + 1] = f1; fis[tid * 6 + 2] = f2;
        fis[tid * 6 + 3] = (q0 + q1 + q2) * inv2;
        fis[tid * 6 + 4] = (q1 + q2) * inv2;
        fis[tid * 6 + 5] = q2 * inv2;
        if (ht == 0) {
            g_dist[t * Bsz + b] = 1.0f - (f0 + f1 + f2) * (1.0f / 3.0f);
            float4 z = make_float4(0.0f, 0.0f, 0.0f, 0.0f);
            *(float4*)&g_p6s[(t + 2) % 3][b][0] = z;   // zero the buffer step t+1 accumulates into
            *(float4*)&g_p6s[(t + 2) % 3][b][4] = z;
        }
    }
    __syncthreads();

    // ---- GEMM: 8 k-blocks; B resident (base advances per blk!), A double-buffered ----
    ull acc[4][2] = {};
    for (int blk = 0; blk < NKB; blk++) {
        if (blk < NKB - 1) ldA(blk + 1);
        const float* Ab = &As[(blk & 1) * 48 * 128];
        const float* Bb = &Bs[blk * BKF * 52];          // <-- fixed: per-block B base
        ulonglong2 a0 = *(const ulonglong2*)&Ab[4 * trow];
        ulonglong2 a1 = *(const ulonglong2*)&Ab[4 * trow + 64];
        float2 b2 = *(const float2*)&Bb[2 * tcol];
#pragma unroll
        for (int kk = 0; kk < BKF; kk++) {
            ulonglong2 na0, na1; float2 nb2;
            if (kk < BKF - 1) {
                na0 = *(const ulonglong2*)&Ab[(kk + 1) * 128 + 4 * trow];
                na1 = *(const ulonglong2*)&Ab[(kk + 1) * 128 + 4 * trow + 64];
                nb2 = *(const float2*)&Bb[(kk + 1) * 52 + 2 * tcol];
            }
            ull b0 = splat2(b2.x), b1 = splat2(b2.y);
            fma2(acc[0][0], a0.x, b0); fma2(acc[0][1], a0.x, b1);
            fma2(acc[1][0], a0.y, b0); fma2(acc[1][1], a0.y, b1);
            fma2(acc[2][0], a1.x, b0); fma2(acc[2][1], a1.x, b1);
            fma2(acc[3][0], a1.y, b0); fma2(acc[3][1], a1.y, b1);
            if (kk < BKF - 1) { a0 = na0; a1 = na1; b2 = nb2; }
        }
        if (blk < NKB - 1) stA((blk + 1) & 1);
        __syncthreads();
    }

    // ---- add GEMM result into xw tile (xs) ----
#pragma unroll
    for (int p = 0; p < 4; p++) {
        int r0 = 4 * trow + (p & 1) * 2 + (p >> 1) * 64;
#pragma unroll
        for (int j = 0; j < 2; j++) {
            int c = 2 * tcol + j;
            float2 x = *(float2*)&xs[c * 128 + r0];
            float2 v = unpk(acc[p][j]);
            x.x += v.x; x.y += v.y;
            *(float2*)&xs[c * 128 + r0] = x;
        }
    }
    __syncthreads();

    // ---- remap: per (b, hcol) gate nonlinearity + state update ----
#pragma unroll
    for (int r = 0; r < 4; r++) {
        int idx = tid + 384 * r;          // 1536 = 128 b x 12 hc
        int b = idx & 127, hc = idx >> 7;
        int h_g = ht * HT + hc;
        int l = h_g >> 7;
        float fg = sigf(xs[(hc * 4 + 0) * 128 + b]);
        float ig = sigf(xs[(hc * 4 + 1) * 128 + b]);
        float og = sigf(xs[(hc * 4 + 2) * 128 + b]);
        float ci = tanhfast(xs[(hc * 4 + 3) * 128 + b]);
        float F = fis[b * 6 + l], I = fis[b * 6 + 3 + l];
        int bg = bm + b;
        float cold = g_cT[h_g][bg];
        float ov = F * I;
        float cn = ov * (fg * cold + ig * ci) + (F - ov) * cold + (I - ov) * ci;
        g_cT[h_g][bg] = cn;
        float hn = og * tanhfast(cn);
        g_hT[wr][h_g][bg] = hn;
        g_hhistT[((size_t)t * Hh + h_g) * Bsz + bg] = hn;
#pragma unroll
        for (int c = 0; c < 6; c++)
            p6p[hc * 780 + b * 6 + c] = hn * rw6[hc * 6 + c];
    }
    __syncthreads();

    // ---- reduce p6 over hcols, accumulate into next step's buffer ----
#pragma unroll
    for (int r = 0; r < 2; r++) {
        int idx = tid + 384 * r;          // 768 = 128 b x 6 c
        int b = idx / 6, c = idx % 6;
        float s = 0.0f;
#pragma unroll
        for (int hc = 0; hc < HT; hc++) s += p6p[hc * 780 + b * 6 + c];
        atomicAdd(&g_p6s[(t + 1) % 3][bm + b][c], s);
    }
}

// ---------------- finalize: per-batch theme/conv/out at t = v_len-1 ----------------
#define GROUP 4
#define FIN_SMEM_FLOATS (GROUP * 3840 + GROUP * Hh + GROUP * Hh + GROUP * 64 + GROUP * Kw + GROUP * Kw + GROUP)
__global__ __launch_bounds__(384) void finalize(
    const int* __restrict__ vlen,
    const float* __restrict__ sw, const float* __restrict__ sb,
    const float* __restrict__ rsw, const float* __restrict__ rsb,
    const float* __restrict__ cw, const float* __restrict__ cb,
    const float* __restrict__ ow, const float* __restrict__ ob,
    float* __restrict__ out) {
    extern __shared__ float sm[];
    float* lh   = sm;
    float* th   = lh + GROUP * 3840;
    float* rn   = th + GROUP * Hh;
    float* s1   = rn + GROUP * Hh;
    float* ldw  = s1 + GROUP * 64;
    float* dtmp = ldw + GROUP * Kw;
    int*   tbs  = (int*)(dtmp + GROUP * Kw);

    const int tid = threadIdx.x;
    const int b0 = blockIdx.x * GROUP;

    if (tid < GROUP) tbs[tid] = vlen[b0 + tid] - 1;
    __syncthreads();
    if (tid < GROUP * Kw) {
        int g = tid / Kw, j = tid % Kw;
        int ts = tbs[g] - (Kw - 1) + j;
        dtmp[g * Kw + j] = (ts >= 0) ? g_dist[ts * Bsz + b0 + g] : 0.0f;
    }
    __syncthreads();
    if (tid < GROUP) {
        float c = 0.0f, cums[Kw];
#pragma unroll
        for (int j = 0; j < Kw; j++) { c += dtmp[tid * Kw + j]; cums[j] = c; }
        float m = cums[Kw - 1];
        float s = 0.0f, e[Kw];
#pragma unroll
        for (int j = 0; j < Kw; j++) { e[j] = __expf(cums[j] - m); s += e[j]; }
        float inv = 1.0f / s;
#pragma unroll
        for (int j = 0; j < Kw; j++) ldw[tid * Kw + j] = e[j] * inv;
    }
    __syncthreads();

    for (int g = 0; g < GROUP; g++) {
        int tb = tbs[g], b = b0 + g;
        float tr = 0.0f;
#pragma unroll
        for (int j = 0; j < Kw; j++) {
            int ts = tb - (Kw - 1) + j;
            float hv = (ts >= 0) ? g_hhistT[((size_t)ts * Hh + tid) * Bsz + b] : 0.0f;
            float v = hv * ldw[g * Kw + j];
            lh[g * 3840 + j * Hh + tid] = v;
            tr += v;
        }
        th[g * Hh + tid] = tr * 0.1f;
    }
    __syncthreads();

    if (tid < GROUP * 64) {
        int g = tid >> 6, j = tid & 63;
        float a = sb[j];
        for (int h = 0; h < Hh; h++) a += th[g * Hh + h] * sw[h * 64 + j];
        s1[g * 64 + j] = fmaxf(a, 0.0f);
    }
    __syncthreads();

    float accv[GROUP];
    float cbv = cb[tid];
#pragma unroll
    for (int g = 0; g < GROUP; g++) accv[g] = cbv;
    const float2* cwp = (const float2*)(cw + (size_t)tid * (Hh * Kw));
    for (int h = 0; h < Hh; h++) {
#pragma unroll
        for (int jp = 0; jp < Kw / 2; jp++) {
            float2 w = cwp[h * (Kw / 2) + jp];
            int j0 = jp * 2;
#pragma unroll
            for (int g = 0; g < GROUP; g++) {
                accv[g] += lh[g * 3840 + j0 * Hh + h] * w.x
                         + lh[g * 3840 + (j0 + 1) * Hh + h] * w.y;
            }
        }
    }

    for (int g = 0; g < GROUP; g++) {
        float a = rsb[tid];
#pragma unroll
        for (int j = 0; j < 64; j++) a += s1[g * 64 + j] * rsw[j * Hh + tid];
        float t2 = sigf(a);
        int tb = tbs[g], b = b0 + g;
        float hf = g_hhistT[((size_t)tb * Hh + tid) * Bsz + b];
        rn[g * Hh + tid] = hf + t2 * accv[g];
    }
    __syncthreads();

    if (tid < GROUP * LAB) {
        int g = tid / LAB, lab = tid % LAB;
        float a = ob[lab];
        for (int h = 0; h < Hh; h++) a += rn[g * Hh + h] * ow[h * LAB + lab];
        out[(b0 + g) * LAB + lab] = a;
    }
}

// ---------------- launch ----------------
#define FUSED_SMEM ((384*52 + 2*48*128 + 48*128 + 12*130*6 + 128*6 + 12*6) * (int)sizeof(float))

extern "C" void kernel_launch(void* const* d_in, const int* in_sizes, int n_in,
                              void* d_out, int out_size) {
    const float* X   = (const float*)d_in[0];
    const int*   vlen= (const int*)  d_in[1];
    const float* kw  = (const float*)d_in[2];
    const float* kb  = (const float*)d_in[3];
    const float* rw  = (const float*)d_in[4];
    const float* rb  = (const float*)d_in[5];
    const float* sw  = (const float*)d_in[6];
    const float* sb  = (const float*)d_in[7];
    const float* rsw = (const float*)d_in[8];
    const float* rsb = (const float*)d_in[9];
    const float* cw  = (const float*)d_in[10];
    const float* cb  = (const float*)d_in[11];
    const float* ow  = (const float*)d_in[12];
    const float* ob  = (const float*)d_in[13];
    float* out = (float*)d_out;

    cudaFuncSetAttribute(finalize, cudaFuncAttributeMaxDynamicSharedMemorySize,
                         FIN_SMEM_FLOATS * (int)sizeof(float));
    cudaFuncSetAttribute(fused_step, cudaFuncAttributeMaxDynamicSharedMemorySize,
                         FUSED_SMEM);

    init_state<<<148, 512>>>();
    prep_B<<<(NHT * Hh * NTW + 255) / 256, 256>>>(rw);
    gemm_xw<<<dim3((GATES + 127) / 128, (Bsz * Tt) / 128), 256>>>(X, kw, kb, rw, rb);
    transpose_xw<<<dim3((GATES + 31) / 32, Bsz / 32, Tt), 256>>>();
    for (int t = 0; t < Tt; t++) {
        fused_step<<<dim3(NHT, Bsz / 128), 384, FUSED_SMEM>>>(rw, t);
    }
    finalize<<<Bsz / GROUP, Hh, FIN_SMEM_FLOATS * (int)sizeof(float)>>>(
        vlen, sw, sb, rsw, rsb, cw, cb, ow, ob, out);
}